// round 2
// baseline (speedup 1.0000x reference)
#include <cuda_runtime.h>
#include <cuda_fp16.h>
#include <mma.h>
#include <math.h>

using namespace nvcuda;

// ---- static problem config ----
#define Nn    10000
#define NTOTc 80000
#define Bg    8
#define Emax  320000
#define Kk    30
#define ZLEN  3841           // K*C + 1

// ---- scratch ----
__device__ float  g_q[Nn * 512];
__device__ __half g_kh[Nn * 512];
__device__ __half g_vh[Nn * 512];
__device__ float  g_hA[(size_t)NTOTc * 128];
__device__ float  g_hB[(size_t)NTOTc * 128];
__device__ int    g_deg[Nn + 1];
__device__ int    g_off[Nn + 1];
__device__ int    g_cur[Nn];
__device__ int    g_srcs[Emax];
__device__ float  g_z[Bg * ZLEN];
__device__ int    g_topk[Bg * Kk];

// ================= CSR build =================
__global__ void zero_deg_kernel() {
    int i = blockIdx.x * blockDim.x + threadIdx.x;
    if (i <= Nn) g_deg[i] = 0;
}
__global__ void hist_kernel(const int* __restrict__ dst, int E) {
    int e = blockIdx.x * blockDim.x + threadIdx.x;
    if (e < E) atomicAdd(&g_deg[dst[e]], 1);
}
__global__ __launch_bounds__(1024) void scan_kernel() {
    __shared__ int partial[1024];
    const int PER = 10;
    int t = threadIdx.x;
    int base = t * PER;
    int local[PER];
    int s = 0;
    #pragma unroll
    for (int i = 0; i < PER; i++) {
        int idx = base + i;
        int dv = (idx < Nn) ? g_deg[idx] : 0;
        local[i] = s; s += dv;
    }
    partial[t] = s;
    __syncthreads();
    for (int offd = 1; offd < 1024; offd <<= 1) {
        int addv = 0;
        if (t >= offd) addv = partial[t - offd];
        __syncthreads();
        if (t >= offd) partial[t] += addv;
        __syncthreads();
    }
    int pre = (t > 0) ? partial[t - 1] : 0;
    #pragma unroll
    for (int i = 0; i < PER; i++) {
        int idx = base + i;
        if (idx < Nn) { int o = pre + local[i]; g_off[idx] = o; g_cur[idx] = o; }
    }
    if (t == 1023) g_off[Nn] = partial[1023];
}
__global__ void scatter_kernel(const int* __restrict__ src,
                               const int* __restrict__ dst, int E) {
    int e = blockIdx.x * blockDim.x + threadIdx.x;
    if (e < E) {
        int d = dst[e];
        int p = atomicAdd(&g_cur[d], 1);
        g_srcs[p] = src[e];
    }
}

// ================= 3xTF32 tensor-core GEMM core pieces =================
// Tile: 64(M) x 64(N) x 128(K), K-chunks of 32. 256 threads (8 warps).
// smem: A_hi[64][40], A_lo[64][40], W_hi[32][72], W_lo[32][72]; epilogue reuses front as Cs[64][72].
#define SM_AH 0
#define SM_AL 2560
#define SM_WH 5120
#define SM_WL 7424
#define SM_TOT 9728

__device__ __forceinline__ void g3t_load_A(float* sm, const float* __restrict__ A,
                                           int row0, int M, int k0, int tid) {
    int r = tid >> 2;
    int cseg = (tid & 3) * 8;
    int gr = row0 + r;
    #pragma unroll
    for (int i = 0; i < 2; i++) {
        float4 va = (gr < M) ? *(const float4*)(A + (size_t)gr * 128 + k0 + cseg + i * 4)
                             : make_float4(0.f, 0.f, 0.f, 0.f);
        float* ph = sm + SM_AH + r * 40 + cseg + i * 4;
        float* pl = sm + SM_AL + r * 40 + cseg + i * 4;
        float h;
        h = wmma::__float_to_tf32(va.x); ph[0] = h; pl[0] = wmma::__float_to_tf32(va.x - h);
        h = wmma::__float_to_tf32(va.y); ph[1] = h; pl[1] = wmma::__float_to_tf32(va.y - h);
        h = wmma::__float_to_tf32(va.z); ph[2] = h; pl[2] = wmma::__float_to_tf32(va.z - h);
        h = wmma::__float_to_tf32(va.w); ph[3] = h; pl[3] = wmma::__float_to_tf32(va.w - h);
    }
}

__device__ __forceinline__ void g3t_load_W(float* sm, const float* __restrict__ W,
                                           int col0, int Nout, int k0, int tid) {
    int r = tid >> 3;
    int cseg = (tid & 7) * 8;
    #pragma unroll
    for (int i = 0; i < 2; i++) {
        float4 vw = *(const float4*)(W + (size_t)(k0 + r) * Nout + col0 + cseg + i * 4);
        float* ph = sm + SM_WH + r * 72 + cseg + i * 4;
        float* pl = sm + SM_WL + r * 72 + cseg + i * 4;
        float h;
        h = wmma::__float_to_tf32(vw.x); ph[0] = h; pl[0] = wmma::__float_to_tf32(vw.x - h);
        h = wmma::__float_to_tf32(vw.y); ph[1] = h; pl[1] = wmma::__float_to_tf32(vw.y - h);
        h = wmma::__float_to_tf32(vw.z); ph[2] = h; pl[2] = wmma::__float_to_tf32(vw.z - h);
        h = wmma::__float_to_tf32(vw.w); ph[3] = h; pl[3] = wmma::__float_to_tf32(vw.w - h);
    }
}

typedef wmma::fragment<wmma::matrix_a, 16, 16, 8, wmma::precision::tf32, wmma::row_major> AFrag;
typedef wmma::fragment<wmma::matrix_b, 16, 16, 8, wmma::precision::tf32, wmma::row_major> BFrag;
typedef wmma::fragment<wmma::accumulator, 16, 16, 8, float> CFrag;

// Full 64x64 tile compute: returns with Cs (= sm[0..4607], ld 72) populated; caller syncs before.
__device__ __forceinline__ void g3t_compute(float* sm, const float* A, const float* W,
                                            int row0, int col0, int M, int Nout, int tid) {
    int warpId = tid >> 5;
    int rb = warpId >> 1;
    int ct0 = (warpId & 1) * 2;
    CFrag cf[2];
    wmma::fill_fragment(cf[0], 0.f);
    wmma::fill_fragment(cf[1], 0.f);

    for (int kc = 0; kc < 4; kc++) {
        int k0 = kc * 32;
        g3t_load_A(sm, A, row0, M, k0, tid);
        g3t_load_W(sm, W, col0, Nout, k0, tid);
        __syncthreads();
        #pragma unroll
        for (int ks = 0; ks < 4; ks++) {
            AFrag aH, aL;
            wmma::load_matrix_sync(aH, sm + SM_AH + (rb * 16) * 40 + ks * 8, 40);
            wmma::load_matrix_sync(aL, sm + SM_AL + (rb * 16) * 40 + ks * 8, 40);
            #pragma unroll
            for (int j = 0; j < 2; j++) {
                BFrag bH, bL;
                wmma::load_matrix_sync(bH, sm + SM_WH + (ks * 8) * 72 + (ct0 + j) * 16, 72);
                wmma::load_matrix_sync(bL, sm + SM_WL + (ks * 8) * 72 + (ct0 + j) * 16, 72);
                wmma::mma_sync(cf[j], aH, bH, cf[j]);
                wmma::mma_sync(cf[j], aH, bL, cf[j]);
                wmma::mma_sync(cf[j], aL, bH, cf[j]);
            }
        }
        __syncthreads();
    }
    // stage C into smem (reuse A area)
    #pragma unroll
    for (int j = 0; j < 2; j++)
        wmma::store_matrix_sync(sm + (rb * 16) * 72 + (ct0 + j) * 16, cf[j], 72, wmma::mem_row_major);
    __syncthreads();
}

// --- QKV GEMM: grid (rowBlks, 8, 3). z=0 -> q(f32), z=1 -> k(f16), z=2 -> v(f16)
__global__ __launch_bounds__(256) void qkv_gemm(
    const float* __restrict__ A,
    const float* __restrict__ Wq, const float* __restrict__ bq,
    const float* __restrict__ Wk, const float* __restrict__ bk,
    const float* __restrict__ Wv, const float* __restrict__ bv)
{
    __shared__ float sm[SM_TOT];
    int tid = threadIdx.x;
    int row0 = blockIdx.x * 64;
    int col0 = blockIdx.y * 64;
    int z = blockIdx.z;
    const float* W = (z == 0) ? Wq : (z == 1) ? Wk : Wv;
    const float* bias = (z == 0) ? bq : (z == 1) ? bk : bv;

    g3t_compute(sm, A, W, row0, col0, Nn, 512, tid);

    #pragma unroll
    for (int i = 0; i < 16; i++) {
        int e = tid + i * 256;
        int r = e >> 6, c = e & 63;
        int gr = row0 + r;
        if (gr >= Nn) continue;
        int gc = col0 + c;
        float val = sm[r * 72 + c] + bias[gc];
        size_t o = (size_t)gr * 512 + gc;
        if (z == 0)      g_q[o]  = val;
        else if (z == 1) g_kh[o] = __float2half(val);
        else             g_vh[o] = __float2half(val);
    }
}

// --- skip GEMM: C = A@Wskip + bskip; rows >= rawRows additionally get BN+ReLU.
__global__ __launch_bounds__(256) void skip_gemm(
    const float* __restrict__ A, const float* __restrict__ W,
    const float* __restrict__ bias, float* __restrict__ C,
    int M, int rawRows,
    const float* __restrict__ bng, const float* __restrict__ bnb,
    const float* __restrict__ bnm, const float* __restrict__ bnv)
{
    __shared__ float sm[SM_TOT];
    int tid = threadIdx.x;
    int row0 = blockIdx.x * 64;
    int col0 = blockIdx.y * 64;

    g3t_compute(sm, A, W, row0, col0, M, 128, tid);

    #pragma unroll
    for (int i = 0; i < 16; i++) {
        int e = tid + i * 256;
        int r = e >> 6, c = e & 63;
        int gr = row0 + r;
        if (gr >= M) continue;
        int gc = col0 + c;
        float val = sm[r * 72 + c] + bias[gc];
        if (gr >= rawRows) {
            float sc = bng[gc] * rsqrtf(bnv[gc] + 1e-5f);
            val = (val - bnm[gc]) * sc + bnb[gc];
            val = fmaxf(val, 0.f);
        }
        C[(size_t)gr * 128 + gc] = val;
    }
}

// ================= fused attention (fp16 K/V, online softmax) =================
__global__ __launch_bounds__(128) void attn_kernel(
    const float* __restrict__ q, const __half* __restrict__ kh,
    const __half* __restrict__ vh, float* __restrict__ hnext,
    const float* __restrict__ bng, const float* __restrict__ bnb,
    const float* __restrict__ bnm, const float* __restrict__ bnv)
{
    int n = blockIdx.x;
    int warp = threadIdx.x >> 5;
    int lane = threadIdx.x & 31;
    __shared__ float outsh[4][128];

    const float4 qr = *(const float4*)(q + (size_t)n * 512 + warp * 128 + lane * 4);
    int b = g_off[n], e = g_off[n + 1];

    float m = -1e30f, d = 0.f;
    float a0 = 0.f, a1 = 0.f, a2 = 0.f, a3 = 0.f;

    for (int ei = b; ei < e; ei++) {
        int s = g_srcs[ei];
        size_t base = (size_t)s * 512 + warp * 128;
        uint2 kr = ((const uint2*)(kh + base))[lane];
        float2 k01 = __half22float2(*(const __half2*)&kr.x);
        float2 k23 = __half22float2(*(const __half2*)&kr.y);
        float p = qr.x * k01.x + qr.y * k01.y + qr.z * k23.x + qr.w * k23.y;
        #pragma unroll
        for (int o = 16; o; o >>= 1) p += __shfl_xor_sync(0xffffffffu, p, o);
        float alpha = p * 0.08838834764831843f;  // 1/sqrt(128)
        float mn = fmaxf(m, alpha);
        float sc = __expf(m - mn);
        float w  = __expf(alpha - mn);
        uint2 vr = ((const uint2*)(vh + base))[lane];
        float2 v01 = __half22float2(*(const __half2*)&vr.x);
        float2 v23 = __half22float2(*(const __half2*)&vr.y);
        d  = d * sc + w;
        a0 = a0 * sc + w * v01.x;
        a1 = a1 * sc + w * v01.y;
        a2 = a2 * sc + w * v23.x;
        a3 = a3 * sc + w * v23.y;
        m = mn;
    }
    float inv = 1.f / (d + 1e-16f);
    outsh[warp][lane * 4 + 0] = a0 * inv;
    outsh[warp][lane * 4 + 1] = a1 * inv;
    outsh[warp][lane * 4 + 2] = a2 * inv;
    outsh[warp][lane * 4 + 3] = a3 * inv;
    __syncthreads();

    int t = threadIdx.x;
    float val = hnext[(size_t)n * 128 + t] +
                0.25f * (outsh[0][t] + outsh[1][t] + outsh[2][t] + outsh[3][t]);
    float sc = bng[t] * rsqrtf(bnv[t] + 1e-5f);
    float r = (val - bnm[t]) * sc + bnb[t];
    hnext[(size_t)n * 128 + t] = fmaxf(r, 0.f);
}

// ================= sort-pool =================
__global__ __launch_bounds__(256) void sortpool_kernel(const float* __restrict__ h,
                                                       const float* __restrict__ age)
{
    int g = blockIdx.x;
    int t = threadIdx.x;
    __shared__ unsigned int skey[Nn];
    __shared__ unsigned long long sbest[256];

    for (int n = t; n < Nn; n += 256) {
        float val = h[((size_t)g * Nn + n) * 128 + 127];
        unsigned int bits = __float_as_uint(val);
        unsigned int enc = (bits & 0x80000000u) ? ~bits : (bits | 0x80000000u);
        skey[n] = enc;
    }
    __syncthreads();

    for (int kk = 0; kk < Kk; kk++) {
        unsigned long long best = 0ull;
        for (int n = t; n < Nn; n += 256) {
            unsigned long long key =
                ((unsigned long long)skey[n] << 32) | (unsigned int)(0xFFFFFFFFu - n);
            if (key > best) best = key;
        }
        sbest[t] = best;
        __syncthreads();
        for (int s = 128; s > 0; s >>= 1) {
            if (t < s) {
                unsigned long long o = sbest[t + s];
                if (o > sbest[t]) sbest[t] = o;
            }
            __syncthreads();
        }
        if (t == 0) {
            int n = (int)(0xFFFFFFFFu - (unsigned int)(sbest[0] & 0xFFFFFFFFull));
            g_topk[g * Kk + kk] = n;
            skey[n] = 0;
        }
        __syncthreads();
    }

    for (int i = t; i < Kk * 128; i += 256) {
        int kkk = i >> 7, c = i & 127;
        int n = g_topk[g * Kk + kkk];
        g_z[g * ZLEN + i] = h[((size_t)g * Nn + n) * 128 + c];
    }
    if (t == 0) g_z[g * ZLEN + Kk * 128] = age[g];
}

// ================= MLP head =================
__global__ __launch_bounds__(512) void mlp_kernel(
    const float* __restrict__ W1, const float* __restrict__ b1,
    const float* __restrict__ W2, const float* __restrict__ b2,
    float* __restrict__ out)
{
    int g = blockIdx.x;
    int t = threadIdx.x;
    __shared__ float zs[ZLEN];
    __shared__ float red0[512];
    __shared__ float red1[512];

    for (int i = t; i < ZLEN; i += 512) zs[i] = g_z[g * ZLEN + i];
    __syncthreads();

    float acc = b1[t];
    for (int j = 0; j < ZLEN; j++) acc += zs[j] * W1[(size_t)j * 512 + t];
    float hid = fmaxf(acc, 0.f);

    red0[t] = hid * W2[t * 2 + 0];
    red1[t] = hid * W2[t * 2 + 1];
    __syncthreads();
    for (int s = 256; s > 0; s >>= 1) {
        if (t < s) { red0[t] += red0[t + s]; red1[t] += red1[t + s]; }
        __syncthreads();
    }
    if (t == 0) {
        float o0 = red0[0] + b2[0];
        float o1 = red1[0] + b2[1];
        float mx = fmaxf(o0, o1);
        float lse = mx + logf(expf(o0 - mx) + expf(o1 - mx));
        out[g * 2 + 0] = o0 - lse;
        out[g * 2 + 1] = o1 - lse;
    }
}

// ================= launch =================
extern "C" void kernel_launch(void* const* d_in, const int* in_sizes, int n_in,
                              void* d_out, int out_size)
{
    const float* x     = (const float*)d_in[0];
    const int*   eidx  = (const int*)  d_in[1];
    const float* age   = (const float*)d_in[2];
    const float* Wq    = (const float*)d_in[3];
    const float* bq    = (const float*)d_in[4];
    const float* Wk    = (const float*)d_in[5];
    const float* bk    = (const float*)d_in[6];
    const float* Wv    = (const float*)d_in[7];
    const float* bv    = (const float*)d_in[8];
    const float* Wsk   = (const float*)d_in[9];
    const float* bsk   = (const float*)d_in[10];
    const float* bn_g  = (const float*)d_in[11];
    const float* bn_b  = (const float*)d_in[12];
    const float* bn_m  = (const float*)d_in[13];
    const float* bn_v  = (const float*)d_in[14];
    const float* W1    = (const float*)d_in[15];
    const float* b1    = (const float*)d_in[16];
    const float* W2    = (const float*)d_in[17];
    const float* b2    = (const float*)d_in[18];
    float* out = (float*)d_out;

    int E = in_sizes[1] / 2;
    const int* src = eidx;
    const int* dst = eidx + E;

    float *q, *hA, *hB;
    __half *kh, *vh;
    cudaGetSymbolAddress((void**)&q,  g_q);
    cudaGetSymbolAddress((void**)&kh, g_kh);
    cudaGetSymbolAddress((void**)&vh, g_vh);
    cudaGetSymbolAddress((void**)&hA, g_hA);
    cudaGetSymbolAddress((void**)&hB, g_hB);

    zero_deg_kernel<<<(Nn + 256) / 256, 256>>>();
    hist_kernel<<<(E + 255) / 256, 256>>>(dst, E);
    scan_kernel<<<1, 1024>>>();
    scatter_kernel<<<(E + 255) / 256, 256>>>(src, dst, E);

    const float* hcur = x;
    float* hnext = hA;
    for (int l = 0; l < 3; l++) {
        dim3 gq((Nn + 63) / 64, 8, 3);
        qkv_gemm<<<gq, 256>>>(hcur, Wq, bq, Wk, bk, Wv, bv);
        dim3 gs((NTOTc + 63) / 64, 2);
        skip_gemm<<<gs, 256>>>(hcur, Wsk, bsk, hnext, NTOTc, Nn,
                               bn_g + l * 128, bn_b + l * 128,
                               bn_m + l * 128, bn_v + l * 128);
        attn_kernel<<<Nn, 128>>>(q, kh, vh, hnext,
                                 bn_g + l * 128, bn_b + l * 128,
                                 bn_m + l * 128, bn_v + l * 128);
        hcur = hnext;
        hnext = (hcur == hA) ? hB : hA;
    }

    sortpool_kernel<<<Bg, 256>>>(hcur, age);
    mlp_kernel<<<Bg, 512>>>(W1, b1, W2, b2, out);
}